// round 7
// baseline (speedup 1.0000x reference)
#include <cuda_runtime.h>
#include <cuda_fp16.h>

// Problem: attention  B=4, H=16, S=2048, D=128, fp32 in/out, additive mask.
// out = softmax(Q K^T / sqrt(D) + mask) V
//
// Design: flash-attention, fp16 tensor cores (mma.sync m16n8k16) with fp32
// accumulation, fp32 softmax. One CTA = 128 query rows x full head.
// 8 warps, each warp owns 16 query rows. K-tile of 64 keys per mainloop iter.
//  - Q fragments live in registers for the whole kernel (scaled by 1/sqrt(D)).
//  - K tile in smem row-major (padded stride), V tile in smem TRANSPOSED
//    (d-major, padded stride) so B-fragments are contiguous half2 LDS.
//  - P (softmax numerator) stays in registers and is repacked directly into
//    the A-fragments of the PV mma (accumulator->A fragment layout identity).
//  - mask is streamed straight from gmem into the score accumulators.

#define S_LEN 2048
#define D_DIM 128
#define MTILE 128
#define NTILE 64
#define NITER (S_LEN / NTILE)   // 32
#define KSTR  136               // halves per Ks row (128 + 8 pad) -> 68 words
#define VSTR  72                // halves per Vt row (64 + 8 pad)  -> 36 words

__device__ __forceinline__ void mma16816(float* c, const unsigned* a,
                                         unsigned b0, unsigned b1) {
    asm volatile(
        "mma.sync.aligned.m16n8k16.row.col.f32.f16.f16.f32 "
        "{%0,%1,%2,%3}, {%4,%5,%6,%7}, {%8,%9}, {%0,%1,%2,%3};\n"
        : "+f"(c[0]), "+f"(c[1]), "+f"(c[2]), "+f"(c[3])
        : "r"(a[0]), "r"(a[1]), "r"(a[2]), "r"(a[3]), "r"(b0), "r"(b1));
}

__device__ __forceinline__ unsigned pack_h2(float a, float b) {
    __half2 h = __floats2half2_rn(a, b);
    return *reinterpret_cast<unsigned*>(&h);
}

__global__ __launch_bounds__(256, 1)
void fa_fp16_kernel(const float* __restrict__ Q, const float* __restrict__ K,
                    const float* __restrict__ V, const float* __restrict__ M,
                    float* __restrict__ O) {
    __shared__ __half Ks[NTILE * KSTR];   // [kv][d]  (padded)
    __shared__ __half Vt[D_DIM * VSTR];   // [d][kv]  (transposed, padded)

    const int tid  = threadIdx.x;
    const int warp = tid >> 5;
    const int lane = tid & 31;
    const int qc   = lane & 3;         // quad column id
    const int lr   = lane >> 2;        // quad row id (0..7)

    const int qtile = blockIdx.x;      // 0..15
    const int bh    = blockIdx.y;      // 0..63
    const int q0    = qtile * MTILE;
    const int r0    = warp * 16 + lr;  // local q row for c0,c1 ; r0+8 for c2,c3

    const float scale = 0.08838834764831845f;  // 1/sqrt(128)

    const float* Qb = Q + ((size_t)bh * S_LEN + q0) * D_DIM;
    const float* Kb = K + (size_t)bh * S_LEN * D_DIM;
    const float* Vb = V + (size_t)bh * S_LEN * D_DIM;
    const float* Mb = M + ((size_t)bh * S_LEN + q0) * S_LEN;
    float*       Ob = O + ((size_t)bh * S_LEN + q0) * D_DIM;

    // ---- Q fragments (A of QK mma), fp16, pre-scaled, resident in regs ----
    // qf[ks][0..3]: ks covers d-cols [16ks,16ks+16)
    unsigned qf[8][4];
#pragma unroll
    for (int ks = 0; ks < 8; ks++) {
        const int c = ks * 16 + qc * 2;
        float2 x0 = *(const float2*)(Qb + (size_t)r0 * D_DIM + c);
        float2 x1 = *(const float2*)(Qb + (size_t)(r0 + 8) * D_DIM + c);
        float2 x2 = *(const float2*)(Qb + (size_t)r0 * D_DIM + c + 8);
        float2 x3 = *(const float2*)(Qb + (size_t)(r0 + 8) * D_DIM + c + 8);
        qf[ks][0] = pack_h2(x0.x * scale, x0.y * scale);
        qf[ks][1] = pack_h2(x1.x * scale, x1.y * scale);
        qf[ks][2] = pack_h2(x2.x * scale, x2.y * scale);
        qf[ks][3] = pack_h2(x3.x * scale, x3.y * scale);
    }

    // online-softmax state (two rows per thread: r0 and r0+8)
    float m0 = -INFINITY, m1 = -INFINITY;
    float l0 = 0.0f, l1 = 0.0f;
    float oacc[16][4];
#pragma unroll
    for (int nd = 0; nd < 16; nd++) {
        oacc[nd][0] = 0.f; oacc[nd][1] = 0.f; oacc[nd][2] = 0.f; oacc[nd][3] = 0.f;
    }

    for (int kt = 0; kt < NITER; kt++) {
        __syncthreads();
        // ---- fill K tile (row-major fp16) ----
        {
            const float4* src = (const float4*)(Kb + (size_t)kt * NTILE * D_DIM);
#pragma unroll
            for (int it = 0; it < 8; it++) {
                const int i = tid + it * 256;          // 2048 float4
                float4 x = src[i];
                const int kv = i >> 5;                 // /32
                const int d  = (i & 31) << 2;          // *4
                __half2* dst = (__half2*)(Ks + kv * KSTR + d);
                dst[0] = __floats2half2_rn(x.x, x.y);
                dst[1] = __floats2half2_rn(x.z, x.w);
            }
        }
        // ---- fill V tile transposed (d-major fp16) ----
        {
            const float4* src = (const float4*)(Vb + (size_t)kt * NTILE * D_DIM);
#pragma unroll
            for (int it = 0; it < 8; it++) {
                const int i = tid + it * 256;
                float4 x = src[i];
                const int kv = i >> 5;
                const int d  = (i & 31) << 2;
                Vt[(d + 0) * VSTR + kv] = __float2half_rn(x.x);
                Vt[(d + 1) * VSTR + kv] = __float2half_rn(x.y);
                Vt[(d + 2) * VSTR + kv] = __float2half_rn(x.z);
                Vt[(d + 3) * VSTR + kv] = __float2half_rn(x.w);
            }
        }
        __syncthreads();

        // ---- S = Q K^T (scaled) ----
        float sacc[8][4];
#pragma unroll
        for (int j = 0; j < 8; j++) {
            sacc[j][0] = 0.f; sacc[j][1] = 0.f; sacc[j][2] = 0.f; sacc[j][3] = 0.f;
        }
#pragma unroll
        for (int ks = 0; ks < 8; ks++) {
#pragma unroll
            for (int j = 0; j < 8; j++) {
                // B fragment: K[kv = 8j + lr][d = 16ks + 2qc + {0,1} (+8)]
                const unsigned* bp =
                    (const unsigned*)(Ks + (j * 8 + lr) * KSTR) + ks * 8 + qc;
                mma16816(sacc[j], qf[ks], bp[0], bp[4]);
            }
        }

        // ---- add mask (streamed from gmem) ----
        {
            const float* mr0 = Mb + (size_t)r0 * S_LEN + kt * NTILE;
            const float* mr1 = mr0 + (size_t)8 * S_LEN;
#pragma unroll
            for (int j = 0; j < 8; j++) {
                float2 u0 = *(const float2*)(mr0 + j * 8 + qc * 2);
                float2 u1 = *(const float2*)(mr1 + j * 8 + qc * 2);
                sacc[j][0] += u0.x; sacc[j][1] += u0.y;
                sacc[j][2] += u1.x; sacc[j][3] += u1.y;
            }
        }

        // ---- online softmax ----
        float tm0 = -INFINITY, tm1 = -INFINITY;
#pragma unroll
        for (int j = 0; j < 8; j++) {
            tm0 = fmaxf(tm0, fmaxf(sacc[j][0], sacc[j][1]));
            tm1 = fmaxf(tm1, fmaxf(sacc[j][2], sacc[j][3]));
        }
        tm0 = fmaxf(tm0, __shfl_xor_sync(0xffffffffu, tm0, 1));
        tm0 = fmaxf(tm0, __shfl_xor_sync(0xffffffffu, tm0, 2));
        tm1 = fmaxf(tm1, __shfl_xor_sync(0xffffffffu, tm1, 1));
        tm1 = fmaxf(tm1, __shfl_xor_sync(0xffffffffu, tm1, 2));

        const float nm0 = fmaxf(m0, tm0);
        const float nm1 = fmaxf(m1, tm1);
        const float al0 = __expf(m0 - nm0);   // exp(-inf)=0 on first tile
        const float al1 = __expf(m1 - nm1);
        m0 = nm0; m1 = nm1;

        unsigned pA[4][4];     // PV A-fragments, built directly from P
        float rs0 = 0.f, rs1 = 0.f;
#pragma unroll
        for (int j = 0; j < 8; j++) {
            float p0 = __expf(sacc[j][0] - nm0);
            float p1 = __expf(sacc[j][1] - nm0);
            float p2 = __expf(sacc[j][2] - nm1);
            float p3 = __expf(sacc[j][3] - nm1);
            rs0 += p0 + p1;
            rs1 += p2 + p3;
            // S-tile j (kv cols 8j..8j+7) is half of PV A k16-tile (j>>1):
            //   even j -> a0/a1 (k<8), odd j -> a2/a3 (k>=8)
            pA[j >> 1][(j & 1) * 2 + 0] = pack_h2(p0, p1);  // row r0
            pA[j >> 1][(j & 1) * 2 + 1] = pack_h2(p2, p3);  // row r0+8
        }
        rs0 += __shfl_xor_sync(0xffffffffu, rs0, 1);
        rs0 += __shfl_xor_sync(0xffffffffu, rs0, 2);
        rs1 += __shfl_xor_sync(0xffffffffu, rs1, 1);
        rs1 += __shfl_xor_sync(0xffffffffu, rs1, 2);
        l0 = l0 * al0 + rs0;
        l1 = l1 * al1 + rs1;

        // rescale running O
#pragma unroll
        for (int nd = 0; nd < 16; nd++) {
            oacc[nd][0] *= al0; oacc[nd][1] *= al0;
            oacc[nd][2] *= al1; oacc[nd][3] *= al1;
        }

        // ---- O += P V ----
#pragma unroll
        for (int kt2 = 0; kt2 < 4; kt2++) {
#pragma unroll
            for (int nd = 0; nd < 16; nd++) {
                // B fragment: V[kv = 16kt2 + 2qc + {0,1} (+8)][d = 8nd + lr]
                const unsigned* bp =
                    (const unsigned*)(Vt + (nd * 8 + lr) * VSTR) + kt2 * 8 + qc;
                mma16816(oacc[nd], pA[kt2], bp[0], bp[4]);
            }
        }
    }

    // ---- epilogue: divide by l, store fp32 ----
    const float inv0 = 1.0f / l0;
    const float inv1 = 1.0f / l1;
#pragma unroll
    for (int nd = 0; nd < 16; nd++) {
        float2 w0 = make_float2(oacc[nd][0] * inv0, oacc[nd][1] * inv0);
        float2 w1 = make_float2(oacc[nd][2] * inv1, oacc[nd][3] * inv1);
        *(float2*)(Ob + (size_t)r0 * D_DIM + nd * 8 + qc * 2) = w0;
        *(float2*)(Ob + (size_t)(r0 + 8) * D_DIM + nd * 8 + qc * 2) = w1;
    }
}

extern "C" void kernel_launch(void* const* d_in, const int* in_sizes, int n_in,
                              void* d_out, int out_size) {
    const float* q = (const float*)d_in[0];
    const float* k = (const float*)d_in[1];
    const float* v = (const float*)d_in[2];
    const float* m = (const float*)d_in[3];
    float* out = (float*)d_out;

    dim3 grid(S_LEN / MTILE, 64);   // 16 q-tiles x (B*H)
    dim3 block(256);
    fa_fp16_kernel<<<grid, block>>>(q, k, v, m, out);
}

// round 8
// speedup vs baseline: 1.0022x; 1.0022x over previous
#include <cuda_runtime.h>
#include <cuda_fp16.h>

// Problem: attention  B=4, H=16, S=2048, D=128, fp32 in/out, additive mask.
// out = softmax(Q K^T / sqrt(D) + mask) V
//
// Design: flash-attention, fp16 tensor cores (mma.sync m16n8k16) with fp32
// accumulation, fp32 softmax. One CTA = 128 query rows x full head.
// 8 warps, each warp owns 16 query rows. K-tile of 64 keys per mainloop iter.
//  - Q fragments live in registers for the whole kernel (scaled by 1/sqrt(D)).
//  - K tile in smem row-major (padded stride), V tile in smem TRANSPOSED
//    (d-major, padded stride) so B-fragments are contiguous half2 LDS.
//  - P (softmax numerator) stays in registers and is repacked directly into
//    the A-fragments of the PV mma (accumulator->A fragment layout identity).
//  - mask is streamed straight from gmem into the score accumulators.

#define S_LEN 2048
#define D_DIM 128
#define MTILE 128
#define NTILE 64
#define NITER (S_LEN / NTILE)   // 32
#define KSTR  136               // halves per Ks row (128 + 8 pad) -> 68 words
#define VSTR  72                // halves per Vt row (64 + 8 pad)  -> 36 words

__device__ __forceinline__ void mma16816(float* c, const unsigned* a,
                                         unsigned b0, unsigned b1) {
    asm volatile(
        "mma.sync.aligned.m16n8k16.row.col.f32.f16.f16.f32 "
        "{%0,%1,%2,%3}, {%4,%5,%6,%7}, {%8,%9}, {%0,%1,%2,%3};\n"
        : "+f"(c[0]), "+f"(c[1]), "+f"(c[2]), "+f"(c[3])
        : "r"(a[0]), "r"(a[1]), "r"(a[2]), "r"(a[3]), "r"(b0), "r"(b1));
}

__device__ __forceinline__ unsigned pack_h2(float a, float b) {
    __half2 h = __floats2half2_rn(a, b);
    return *reinterpret_cast<unsigned*>(&h);
}

__global__ __launch_bounds__(256, 1)
void fa_fp16_kernel(const float* __restrict__ Q, const float* __restrict__ K,
                    const float* __restrict__ V, const float* __restrict__ M,
                    float* __restrict__ O) {
    __shared__ __half Ks[NTILE * KSTR];   // [kv][d]  (padded)
    __shared__ __half Vt[D_DIM * VSTR];   // [d][kv]  (transposed, padded)

    const int tid  = threadIdx.x;
    const int warp = tid >> 5;
    const int lane = tid & 31;
    const int qc   = lane & 3;         // quad column id
    const int lr   = lane >> 2;        // quad row id (0..7)

    const int qtile = blockIdx.x;      // 0..15
    const int bh    = blockIdx.y;      // 0..63
    const int q0    = qtile * MTILE;
    const int r0    = warp * 16 + lr;  // local q row for c0,c1 ; r0+8 for c2,c3

    const float scale = 0.08838834764831845f;  // 1/sqrt(128)

    const float* Qb = Q + ((size_t)bh * S_LEN + q0) * D_DIM;
    const float* Kb = K + (size_t)bh * S_LEN * D_DIM;
    const float* Vb = V + (size_t)bh * S_LEN * D_DIM;
    const float* Mb = M + ((size_t)bh * S_LEN + q0) * S_LEN;
    float*       Ob = O + ((size_t)bh * S_LEN + q0) * D_DIM;

    // ---- Q fragments (A of QK mma), fp16, pre-scaled, resident in regs ----
    // qf[ks][0..3]: ks covers d-cols [16ks,16ks+16)
    unsigned qf[8][4];
#pragma unroll
    for (int ks = 0; ks < 8; ks++) {
        const int c = ks * 16 + qc * 2;
        float2 x0 = *(const float2*)(Qb + (size_t)r0 * D_DIM + c);
        float2 x1 = *(const float2*)(Qb + (size_t)(r0 + 8) * D_DIM + c);
        float2 x2 = *(const float2*)(Qb + (size_t)r0 * D_DIM + c + 8);
        float2 x3 = *(const float2*)(Qb + (size_t)(r0 + 8) * D_DIM + c + 8);
        qf[ks][0] = pack_h2(x0.x * scale, x0.y * scale);
        qf[ks][1] = pack_h2(x1.x * scale, x1.y * scale);
        qf[ks][2] = pack_h2(x2.x * scale, x2.y * scale);
        qf[ks][3] = pack_h2(x3.x * scale, x3.y * scale);
    }

    // online-softmax state (two rows per thread: r0 and r0+8)
    float m0 = -INFINITY, m1 = -INFINITY;
    float l0 = 0.0f, l1 = 0.0f;
    float oacc[16][4];
#pragma unroll
    for (int nd = 0; nd < 16; nd++) {
        oacc[nd][0] = 0.f; oacc[nd][1] = 0.f; oacc[nd][2] = 0.f; oacc[nd][3] = 0.f;
    }

    for (int kt = 0; kt < NITER; kt++) {
        __syncthreads();
        // ---- fill K tile (row-major fp16) ----
        {
            const float4* src = (const float4*)(Kb + (size_t)kt * NTILE * D_DIM);
#pragma unroll
            for (int it = 0; it < 8; it++) {
                const int i = tid + it * 256;          // 2048 float4
                float4 x = src[i];
                const int kv = i >> 5;                 // /32
                const int d  = (i & 31) << 2;          // *4
                __half2* dst = (__half2*)(Ks + kv * KSTR + d);
                dst[0] = __floats2half2_rn(x.x, x.y);
                dst[1] = __floats2half2_rn(x.z, x.w);
            }
        }
        // ---- fill V tile transposed (d-major fp16) ----
        {
            const float4* src = (const float4*)(Vb + (size_t)kt * NTILE * D_DIM);
#pragma unroll
            for (int it = 0; it < 8; it++) {
                const int i = tid + it * 256;
                float4 x = src[i];
                const int kv = i >> 5;
                const int d  = (i & 31) << 2;
                Vt[(d + 0) * VSTR + kv] = __float2half_rn(x.x);
                Vt[(d + 1) * VSTR + kv] = __float2half_rn(x.y);
                Vt[(d + 2) * VSTR + kv] = __float2half_rn(x.z);
                Vt[(d + 3) * VSTR + kv] = __float2half_rn(x.w);
            }
        }
        __syncthreads();

        // ---- S = Q K^T (scaled) ----
        float sacc[8][4];
#pragma unroll
        for (int j = 0; j < 8; j++) {
            sacc[j][0] = 0.f; sacc[j][1] = 0.f; sacc[j][2] = 0.f; sacc[j][3] = 0.f;
        }
#pragma unroll
        for (int ks = 0; ks < 8; ks++) {
#pragma unroll
            for (int j = 0; j < 8; j++) {
                // B fragment: K[kv = 8j + lr][d = 16ks + 2qc + {0,1} (+8)]
                const unsigned* bp =
                    (const unsigned*)(Ks + (j * 8 + lr) * KSTR) + ks * 8 + qc;
                mma16816(sacc[j], qf[ks], bp[0], bp[4]);
            }
        }

        // ---- add mask (streamed from gmem) ----
        {
            const float* mr0 = Mb + (size_t)r0 * S_LEN + kt * NTILE;
            const float* mr1 = mr0 + (size_t)8 * S_LEN;
#pragma unroll
            for (int j = 0; j < 8; j++) {
                float2 u0 = *(const float2*)(mr0 + j * 8 + qc * 2);
                float2 u1 = *(const float2*)(mr1 + j * 8 + qc * 2);
                sacc[j][0] += u0.x; sacc[j][1] += u0.y;
                sacc[j][2] += u1.x; sacc[j][3] += u1.y;
            }
        }

        // ---- online softmax ----
        float tm0 = -INFINITY, tm1 = -INFINITY;
#pragma unroll
        for (int j = 0; j < 8; j++) {
            tm0 = fmaxf(tm0, fmaxf(sacc[j][0], sacc[j][1]));
            tm1 = fmaxf(tm1, fmaxf(sacc[j][2], sacc[j][3]));
        }
        tm0 = fmaxf(tm0, __shfl_xor_sync(0xffffffffu, tm0, 1));
        tm0 = fmaxf(tm0, __shfl_xor_sync(0xffffffffu, tm0, 2));
        tm1 = fmaxf(tm1, __shfl_xor_sync(0xffffffffu, tm1, 1));
        tm1 = fmaxf(tm1, __shfl_xor_sync(0xffffffffu, tm1, 2));

        const float nm0 = fmaxf(m0, tm0);
        const float nm1 = fmaxf(m1, tm1);
        const float al0 = __expf(m0 - nm0);   // exp(-inf)=0 on first tile
        const float al1 = __expf(m1 - nm1);
        m0 = nm0; m1 = nm1;

        unsigned pA[4][4];     // PV A-fragments, built directly from P
        float rs0 = 0.f, rs1 = 0.f;
#pragma unroll
        for (int j = 0; j < 8; j++) {
            float p0 = __expf(sacc[j][0] - nm0);
            float p1 = __expf(sacc[j][1] - nm0);
            float p2 = __expf(sacc[j][2] - nm1);
            float p3 = __expf(sacc[j][3] - nm1);
            rs0 += p0 + p1;
            rs1 += p2 + p3;
            // S-tile j (kv cols 8j..8j+7) is half of PV A k16-tile (j>>1):
            //   even j -> a0/a1 (k<8), odd j -> a2/a3 (k>=8)
            pA[j >> 1][(j & 1) * 2 + 0] = pack_h2(p0, p1);  // row r0
            pA[j >> 1][(j & 1) * 2 + 1] = pack_h2(p2, p3);  // row r0+8
        }
        rs0 += __shfl_xor_sync(0xffffffffu, rs0, 1);
        rs0 += __shfl_xor_sync(0xffffffffu, rs0, 2);
        rs1 += __shfl_xor_sync(0xffffffffu, rs1, 1);
        rs1 += __shfl_xor_sync(0xffffffffu, rs1, 2);
        l0 = l0 * al0 + rs0;
        l1 = l1 * al1 + rs1;

        // rescale running O
#pragma unroll
        for (int nd = 0; nd < 16; nd++) {
            oacc[nd][0] *= al0; oacc[nd][1] *= al0;
            oacc[nd][2] *= al1; oacc[nd][3] *= al1;
        }

        // ---- O += P V ----
#pragma unroll
        for (int kt2 = 0; kt2 < 4; kt2++) {
#pragma unroll
            for (int nd = 0; nd < 16; nd++) {
                // B fragment: V[kv = 16kt2 + 2qc + {0,1} (+8)][d = 8nd + lr]
                const unsigned* bp =
                    (const unsigned*)(Vt + (nd * 8 + lr) * VSTR) + kt2 * 8 + qc;
                mma16816(oacc[nd], pA[kt2], bp[0], bp[4]);
            }
        }
    }

    // ---- epilogue: divide by l, store fp32 ----
    const float inv0 = 1.0f / l0;
    const float inv1 = 1.0f / l1;
#pragma unroll
    for (int nd = 0; nd < 16; nd++) {
        float2 w0 = make_float2(oacc[nd][0] * inv0, oacc[nd][1] * inv0);
        float2 w1 = make_float2(oacc[nd][2] * inv1, oacc[nd][3] * inv1);
        *(float2*)(Ob + (size_t)r0 * D_DIM + nd * 8 + qc * 2) = w0;
        *(float2*)(Ob + (size_t)(r0 + 8) * D_DIM + nd * 8 + qc * 2) = w1;
    }
}

extern "C" void kernel_launch(void* const* d_in, const int* in_sizes, int n_in,
                              void* d_out, int out_size) {
    const float* q = (const float*)d_in[0];
    const float* k = (const float*)d_in[1];
    const float* v = (const float*)d_in[2];
    const float* m = (const float*)d_in[3];
    float* out = (float*)d_out;

    dim3 grid(S_LEN / MTILE, 64);   // 16 q-tiles x (B*H)
    dim3 block(256);
    fa_fp16_kernel<<<grid, block>>>(q, k, v, m, out);
}

// round 9
// speedup vs baseline: 1.7704x; 1.7666x over previous
#include <cuda_runtime.h>
#include <cuda_fp16.h>

// Flash attention, B=4 H=16 S=2048 D=128, fp32 in/out, additive mask.
// fp16 mma.sync m16n8k16 with fp32 accum, fp32 softmax (exp2 domain).
// CTA = 128 q rows x full head, 8 warps (16 q rows each), 64-key tiles.
//  - K and V both stored row-major fp16 in smem (stride 136 halves, pad).
//  - QK B-frags via ldmatrix.x4 ; PV B-frags via ldmatrix.x4.trans.
//  - Double-buffered tiles, register prefetch of next tile, 1 barrier/iter.

#define S_LEN 2048
#define D_DIM 128
#define MTILE 128
#define NTILE 64
#define NITER (S_LEN / NTILE)        // 32
#define KSTR  136                    // halves per smem row (128 + 8 pad)
#define TILEH (NTILE * KSTR)         // 8704 halves per tile buffer
#define SMEM_BYTES (4 * TILEH * 2)   // 2 K bufs + 2 V bufs = 69632 B

__device__ __forceinline__ void mma16816(float* c, const unsigned* a,
                                         unsigned b0, unsigned b1) {
    asm volatile(
        "mma.sync.aligned.m16n8k16.row.col.f32.f16.f16.f32 "
        "{%0,%1,%2,%3}, {%4,%5,%6,%7}, {%8,%9}, {%0,%1,%2,%3};\n"
        : "+f"(c[0]), "+f"(c[1]), "+f"(c[2]), "+f"(c[3])
        : "r"(a[0]), "r"(a[1]), "r"(a[2]), "r"(a[3]), "r"(b0), "r"(b1));
}

__device__ __forceinline__ void ldsm_x4(unsigned& r0, unsigned& r1,
                                        unsigned& r2, unsigned& r3,
                                        const __half* p) {
    unsigned a = (unsigned)__cvta_generic_to_shared(p);
    asm volatile("ldmatrix.sync.aligned.m8n8.x4.shared.b16 {%0,%1,%2,%3}, [%4];\n"
                 : "=r"(r0), "=r"(r1), "=r"(r2), "=r"(r3) : "r"(a));
}

__device__ __forceinline__ void ldsm_x4_t(unsigned& r0, unsigned& r1,
                                          unsigned& r2, unsigned& r3,
                                          const __half* p) {
    unsigned a = (unsigned)__cvta_generic_to_shared(p);
    asm volatile("ldmatrix.sync.aligned.m8n8.x4.trans.shared.b16 {%0,%1,%2,%3}, [%4];\n"
                 : "=r"(r0), "=r"(r1), "=r"(r2), "=r"(r3) : "r"(a));
}

__device__ __forceinline__ unsigned pack_h2(float a, float b) {
    __half2 h = __floats2half2_rn(a, b);
    return *reinterpret_cast<unsigned*>(&h);
}

__device__ __forceinline__ float ex2(float x) {
    float r;
    asm("ex2.approx.f32 %0, %1;" : "=f"(r) : "f"(x));
    return r;
}

__global__ __launch_bounds__(256, 1)
void fa_fp16_kernel(const float* __restrict__ Q, const float* __restrict__ K,
                    const float* __restrict__ V, const float* __restrict__ M,
                    float* __restrict__ O) {
    extern __shared__ __half sh[];
    __half* Ksb = sh;                 // [2][TILEH]  row-major [kv][d]
    __half* Vsb = sh + 2 * TILEH;     // [2][TILEH]  row-major [kv][d]

    const int tid  = threadIdx.x;
    const int warp = tid >> 5;
    const int lane = tid & 31;
    const int qc   = lane & 3;
    const int lr   = lane >> 2;

    const int q0 = blockIdx.x * MTILE;
    const int bh = blockIdx.y;
    const int r0 = warp * 16 + lr;

    // scale includes log2(e): softmax computed in exp2 domain
    const float LOG2E = 1.4426950408889634f;
    const float scale = 0.08838834764831845f * LOG2E;

    const float* Qb = Q + ((size_t)bh * S_LEN + q0) * D_DIM;
    const float* Kb = K + (size_t)bh * S_LEN * D_DIM;
    const float* Vb = V + (size_t)bh * S_LEN * D_DIM;
    const float* Mb = M + ((size_t)bh * S_LEN + q0) * S_LEN;
    float*       Ob = O + ((size_t)bh * S_LEN + q0) * D_DIM;

    // per-lane ldmatrix row offsets (halves)
    const int t8 = lane >> 3, r8 = lane & 7;
    const int offK = ((t8 >> 1) * 8 + r8) * KSTR + (t8 & 1) * 8;  // QK tiles
    const int offV = ((t8 & 1) * 8 + r8) * KSTR + (t8 >> 1) * 8;  // PV tiles

    // ---- Q fragments (A of QK mma), fp16, pre-scaled, resident ----
    unsigned qf[8][4];
#pragma unroll
    for (int ks = 0; ks < 8; ks++) {
        const int c = ks * 16 + qc * 2;
        float2 x0 = *(const float2*)(Qb + (size_t)r0 * D_DIM + c);
        float2 x1 = *(const float2*)(Qb + (size_t)(r0 + 8) * D_DIM + c);
        float2 x2 = *(const float2*)(Qb + (size_t)r0 * D_DIM + c + 8);
        float2 x3 = *(const float2*)(Qb + (size_t)(r0 + 8) * D_DIM + c + 8);
        qf[ks][0] = pack_h2(x0.x * scale, x0.y * scale);
        qf[ks][1] = pack_h2(x1.x * scale, x1.y * scale);
        qf[ks][2] = pack_h2(x2.x * scale, x2.y * scale);
        qf[ks][3] = pack_h2(x3.x * scale, x3.y * scale);
    }

    float m0 = -INFINITY, m1 = -INFINITY;
    float l0 = 0.0f, l1 = 0.0f;
    float oacc[16][4];
#pragma unroll
    for (int nd = 0; nd < 16; nd++) {
        oacc[nd][0] = 0.f; oacc[nd][1] = 0.f; oacc[nd][2] = 0.f; oacc[nd][3] = 0.f;
    }

    // ---- prologue: fill tile 0 into buffer 0 ----
    {
        const float4* ks = (const float4*)Kb;
        const float4* vs = (const float4*)Vb;
        float4 kx[8], vx[8];
#pragma unroll
        for (int i = 0; i < 8; i++) { kx[i] = ks[tid + i * 256]; vx[i] = vs[tid + i * 256]; }
#pragma unroll
        for (int i = 0; i < 8; i++) {
            const int idx = tid + i * 256;
            const int kv = idx >> 5, d = (idx & 31) << 2;
            __half2* dk = (__half2*)(Ksb + kv * KSTR + d);
            dk[0] = __floats2half2_rn(kx[i].x, kx[i].y);
            dk[1] = __floats2half2_rn(kx[i].z, kx[i].w);
            __half2* dv = (__half2*)(Vsb + kv * KSTR + d);
            dv[0] = __floats2half2_rn(vx[i].x, vx[i].y);
            dv[1] = __floats2half2_rn(vx[i].z, vx[i].w);
        }
    }
    __syncthreads();

    int buf = 0;
    for (int kt = 0; kt < NITER; kt++) {
        // ---- prefetch next tile into registers (hidden behind MMAs) ----
        float4 kx[8], vx[8];
        const bool pre = (kt + 1 < NITER);
        if (pre) {
            const float4* ks = (const float4*)(Kb + (size_t)(kt + 1) * NTILE * D_DIM);
            const float4* vs = (const float4*)(Vb + (size_t)(kt + 1) * NTILE * D_DIM);
#pragma unroll
            for (int i = 0; i < 8; i++) { kx[i] = ks[tid + i * 256]; vx[i] = vs[tid + i * 256]; }
        }

        // ---- S = Q K^T (ldmatrix.x4 B-fragments) ----
        const __half* kbuf = Ksb + buf * TILEH + offK;
        float sacc[8][4];
#pragma unroll
        for (int j = 0; j < 8; j++) {
            sacc[j][0] = 0.f; sacc[j][1] = 0.f; sacc[j][2] = 0.f; sacc[j][3] = 0.f;
        }
#pragma unroll
        for (int ks = 0; ks < 8; ks++) {
#pragma unroll
            for (int jp = 0; jp < 4; jp++) {
                unsigned b0, b1, b2, b3;
                ldsm_x4(b0, b1, b2, b3, kbuf + jp * (16 * KSTR) + ks * 16);
                mma16816(sacc[2 * jp + 0], qf[ks], b0, b1);
                mma16816(sacc[2 * jp + 1], qf[ks], b2, b3);
            }
        }

        // ---- add mask (x log2e, via FFMA) ----
        {
            const float* mr0 = Mb + (size_t)r0 * S_LEN + kt * NTILE;
            const float* mr1 = mr0 + (size_t)8 * S_LEN;
#pragma unroll
            for (int j = 0; j < 8; j++) {
                float2 u0 = *(const float2*)(mr0 + j * 8 + qc * 2);
                float2 u1 = *(const float2*)(mr1 + j * 8 + qc * 2);
                sacc[j][0] = fmaf(u0.x, LOG2E, sacc[j][0]);
                sacc[j][1] = fmaf(u0.y, LOG2E, sacc[j][1]);
                sacc[j][2] = fmaf(u1.x, LOG2E, sacc[j][2]);
                sacc[j][3] = fmaf(u1.y, LOG2E, sacc[j][3]);
            }
        }

        // ---- online softmax (exp2 domain) ----
        float tm0 = -INFINITY, tm1 = -INFINITY;
#pragma unroll
        for (int j = 0; j < 8; j++) {
            tm0 = fmaxf(tm0, fmaxf(sacc[j][0], sacc[j][1]));
            tm1 = fmaxf(tm1, fmaxf(sacc[j][2], sacc[j][3]));
        }
        tm0 = fmaxf(tm0, __shfl_xor_sync(0xffffffffu, tm0, 1));
        tm0 = fmaxf(tm0, __shfl_xor_sync(0xffffffffu, tm0, 2));
        tm1 = fmaxf(tm1, __shfl_xor_sync(0xffffffffu, tm1, 1));
        tm1 = fmaxf(tm1, __shfl_xor_sync(0xffffffffu, tm1, 2));

        const float nm0 = fmaxf(m0, tm0);
        const float nm1 = fmaxf(m1, tm1);
        const float al0 = ex2(m0 - nm0);   // ex2(-inf)=0 on first tile
        const float al1 = ex2(m1 - nm1);
        m0 = nm0; m1 = nm1;

        unsigned pA[4][4];
        float rs0 = 0.f, rs1 = 0.f;
#pragma unroll
        for (int j = 0; j < 8; j++) {
            float p0 = ex2(sacc[j][0] - nm0);
            float p1 = ex2(sacc[j][1] - nm0);
            float p2 = ex2(sacc[j][2] - nm1);
            float p3 = ex2(sacc[j][3] - nm1);
            rs0 += p0 + p1;
            rs1 += p2 + p3;
            pA[j >> 1][(j & 1) * 2 + 0] = pack_h2(p0, p1);
            pA[j >> 1][(j & 1) * 2 + 1] = pack_h2(p2, p3);
        }
        rs0 += __shfl_xor_sync(0xffffffffu, rs0, 1);
        rs0 += __shfl_xor_sync(0xffffffffu, rs0, 2);
        rs1 += __shfl_xor_sync(0xffffffffu, rs1, 1);
        rs1 += __shfl_xor_sync(0xffffffffu, rs1, 2);
        l0 = l0 * al0 + rs0;
        l1 = l1 * al1 + rs1;

#pragma unroll
        for (int nd = 0; nd < 16; nd++) {
            oacc[nd][0] *= al0; oacc[nd][1] *= al0;
            oacc[nd][2] *= al1; oacc[nd][3] *= al1;
        }

        // ---- O += P V (ldmatrix.x4.trans B-fragments) ----
        const __half* vbuf = Vsb + buf * TILEH + offV;
#pragma unroll
        for (int kt2 = 0; kt2 < 4; kt2++) {
#pragma unroll
            for (int ndp = 0; ndp < 8; ndp++) {
                unsigned b0, b1, b2, b3;
                ldsm_x4_t(b0, b1, b2, b3, vbuf + kt2 * (16 * KSTR) + ndp * 16);
                mma16816(oacc[2 * ndp + 0], pA[kt2], b0, b1);
                mma16816(oacc[2 * ndp + 1], pA[kt2], b2, b3);
            }
        }

        // ---- store prefetched tile into the other buffer ----
        if (pre) {
            __half* kd = Ksb + (buf ^ 1) * TILEH;
            __half* vd = Vsb + (buf ^ 1) * TILEH;
#pragma unroll
            for (int i = 0; i < 8; i++) {
                const int idx = tid + i * 256;
                const int kv = idx >> 5, d = (idx & 31) << 2;
                __half2* dk = (__half2*)(kd + kv * KSTR + d);
                dk[0] = __floats2half2_rn(kx[i].x, kx[i].y);
                dk[1] = __floats2half2_rn(kx[i].z, kx[i].w);
                __half2* dv = (__half2*)(vd + kv * KSTR + d);
                dv[0] = __floats2half2_rn(vx[i].x, vx[i].y);
                dv[1] = __floats2half2_rn(vx[i].z, vx[i].w);
            }
            __syncthreads();
        }
        buf ^= 1;
    }

    // ---- epilogue ----
    const float inv0 = 1.0f / l0;
    const float inv1 = 1.0f / l1;
#pragma unroll
    for (int nd = 0; nd < 16; nd++) {
        float2 w0 = make_float2(oacc[nd][0] * inv0, oacc[nd][1] * inv0);
        float2 w1 = make_float2(oacc[nd][2] * inv1, oacc[nd][3] * inv1);
        *(float2*)(Ob + (size_t)r0 * D_DIM + nd * 8 + qc * 2) = w0;
        *(float2*)(Ob + (size_t)(r0 + 8) * D_DIM + nd * 8 + qc * 2) = w1;
    }
}

extern "C" void kernel_launch(void* const* d_in, const int* in_sizes, int n_in,
                              void* d_out, int out_size) {
    const float* q = (const float*)d_in[0];
    const float* k = (const float*)d_in[1];
    const float* v = (const float*)d_in[2];
    const float* m = (const float*)d_in[3];
    float* out = (float*)d_out;

    cudaFuncSetAttribute(fa_fp16_kernel,
                         cudaFuncAttributeMaxDynamicSharedMemorySize, SMEM_BYTES);

    dim3 grid(S_LEN / MTILE, 64);
    dim3 block(256);
    fa_fp16_kernel<<<grid, block, SMEM_BYTES>>>(q, k, v, m, out);
}

// round 10
// speedup vs baseline: 1.7705x; 1.0000x over previous
#include <cuda_runtime.h>
#include <cuda_fp16.h>

// Flash attention, B=4 H=16 S=2048 D=128, fp32 in/out, additive mask.
// fp16 mma.sync m16n8k16 with fp32 accum, fp32 softmax (exp2 domain).
// CTA = 128 q rows x full head, 8 warps (16 q rows each), 64-key tiles.
//  - K and V both stored row-major fp16 in smem (stride 136 halves, pad).
//  - QK B-frags via ldmatrix.x4 ; PV B-frags via ldmatrix.x4.trans.
//  - Double-buffered tiles, register prefetch of next tile, 1 barrier/iter.

#define S_LEN 2048
#define D_DIM 128
#define MTILE 128
#define NTILE 64
#define NITER (S_LEN / NTILE)        // 32
#define KSTR  136                    // halves per smem row (128 + 8 pad)
#define TILEH (NTILE * KSTR)         // 8704 halves per tile buffer
#define SMEM_BYTES (4 * TILEH * 2)   // 2 K bufs + 2 V bufs = 69632 B

__device__ __forceinline__ void mma16816(float* c, const unsigned* a,
                                         unsigned b0, unsigned b1) {
    asm volatile(
        "mma.sync.aligned.m16n8k16.row.col.f32.f16.f16.f32 "
        "{%0,%1,%2,%3}, {%4,%5,%6,%7}, {%8,%9}, {%0,%1,%2,%3};\n"
        : "+f"(c[0]), "+f"(c[1]), "+f"(c[2]), "+f"(c[3])
        : "r"(a[0]), "r"(a[1]), "r"(a[2]), "r"(a[3]), "r"(b0), "r"(b1));
}

__device__ __forceinline__ void ldsm_x4(unsigned& r0, unsigned& r1,
                                        unsigned& r2, unsigned& r3,
                                        const __half* p) {
    unsigned a = (unsigned)__cvta_generic_to_shared(p);
    asm volatile("ldmatrix.sync.aligned.m8n8.x4.shared.b16 {%0,%1,%2,%3}, [%4];\n"
                 : "=r"(r0), "=r"(r1), "=r"(r2), "=r"(r3) : "r"(a));
}

__device__ __forceinline__ void ldsm_x4_t(unsigned& r0, unsigned& r1,
                                          unsigned& r2, unsigned& r3,
                                          const __half* p) {
    unsigned a = (unsigned)__cvta_generic_to_shared(p);
    asm volatile("ldmatrix.sync.aligned.m8n8.x4.trans.shared.b16 {%0,%1,%2,%3}, [%4];\n"
                 : "=r"(r0), "=r"(r1), "=r"(r2), "=r"(r3) : "r"(a));
}

__device__ __forceinline__ unsigned pack_h2(float a, float b) {
    __half2 h = __floats2half2_rn(a, b);
    return *reinterpret_cast<unsigned*>(&h);
}

__device__ __forceinline__ float ex2(float x) {
    float r;
    asm("ex2.approx.f32 %0, %1;" : "=f"(r) : "f"(x));
    return r;
}

__global__ __launch_bounds__(256, 1)
void fa_fp16_kernel(const float* __restrict__ Q, const float* __restrict__ K,
                    const float* __restrict__ V, const float* __restrict__ M,
                    float* __restrict__ O) {
    extern __shared__ __half sh[];
    __half* Ksb = sh;                 // [2][TILEH]  row-major [kv][d]
    __half* Vsb = sh + 2 * TILEH;     // [2][TILEH]  row-major [kv][d]

    const int tid  = threadIdx.x;
    const int warp = tid >> 5;
    const int lane = tid & 31;
    const int qc   = lane & 3;
    const int lr   = lane >> 2;

    const int q0 = blockIdx.x * MTILE;
    const int bh = blockIdx.y;
    const int r0 = warp * 16 + lr;

    // scale includes log2(e): softmax computed in exp2 domain
    const float LOG2E = 1.4426950408889634f;
    const float scale = 0.08838834764831845f * LOG2E;

    const float* Qb = Q + ((size_t)bh * S_LEN + q0) * D_DIM;
    const float* Kb = K + (size_t)bh * S_LEN * D_DIM;
    const float* Vb = V + (size_t)bh * S_LEN * D_DIM;
    const float* Mb = M + ((size_t)bh * S_LEN + q0) * S_LEN;
    float*       Ob = O + ((size_t)bh * S_LEN + q0) * D_DIM;

    // per-lane ldmatrix row offsets (halves)
    const int t8 = lane >> 3, r8 = lane & 7;
    const int offK = ((t8 >> 1) * 8 + r8) * KSTR + (t8 & 1) * 8;  // QK tiles
    const int offV = ((t8 & 1) * 8 + r8) * KSTR + (t8 >> 1) * 8;  // PV tiles

    // ---- Q fragments (A of QK mma), fp16, pre-scaled, resident ----
    unsigned qf[8][4];
#pragma unroll
    for (int ks = 0; ks < 8; ks++) {
        const int c = ks * 16 + qc * 2;
        float2 x0 = *(const float2*)(Qb + (size_t)r0 * D_DIM + c);
        float2 x1 = *(const float2*)(Qb + (size_t)(r0 + 8) * D_DIM + c);
        float2 x2 = *(const float2*)(Qb + (size_t)r0 * D_DIM + c + 8);
        float2 x3 = *(const float2*)(Qb + (size_t)(r0 + 8) * D_DIM + c + 8);
        qf[ks][0] = pack_h2(x0.x * scale, x0.y * scale);
        qf[ks][1] = pack_h2(x1.x * scale, x1.y * scale);
        qf[ks][2] = pack_h2(x2.x * scale, x2.y * scale);
        qf[ks][3] = pack_h2(x3.x * scale, x3.y * scale);
    }

    float m0 = -INFINITY, m1 = -INFINITY;
    float l0 = 0.0f, l1 = 0.0f;
    float oacc[16][4];
#pragma unroll
    for (int nd = 0; nd < 16; nd++) {
        oacc[nd][0] = 0.f; oacc[nd][1] = 0.f; oacc[nd][2] = 0.f; oacc[nd][3] = 0.f;
    }

    // ---- prologue: fill tile 0 into buffer 0 ----
    {
        const float4* ks = (const float4*)Kb;
        const float4* vs = (const float4*)Vb;
        float4 kx[8], vx[8];
#pragma unroll
        for (int i = 0; i < 8; i++) { kx[i] = ks[tid + i * 256]; vx[i] = vs[tid + i * 256]; }
#pragma unroll
        for (int i = 0; i < 8; i++) {
            const int idx = tid + i * 256;
            const int kv = idx >> 5, d = (idx & 31) << 2;
            __half2* dk = (__half2*)(Ksb + kv * KSTR + d);
            dk[0] = __floats2half2_rn(kx[i].x, kx[i].y);
            dk[1] = __floats2half2_rn(kx[i].z, kx[i].w);
            __half2* dv = (__half2*)(Vsb + kv * KSTR + d);
            dv[0] = __floats2half2_rn(vx[i].x, vx[i].y);
            dv[1] = __floats2half2_rn(vx[i].z, vx[i].w);
        }
    }
    __syncthreads();

    int buf = 0;
    for (int kt = 0; kt < NITER; kt++) {
        // ---- prefetch next tile into registers (hidden behind MMAs) ----
        float4 kx[8], vx[8];
        const bool pre = (kt + 1 < NITER);
        if (pre) {
            const float4* ks = (const float4*)(Kb + (size_t)(kt + 1) * NTILE * D_DIM);
            const float4* vs = (const float4*)(Vb + (size_t)(kt + 1) * NTILE * D_DIM);
#pragma unroll
            for (int i = 0; i < 8; i++) { kx[i] = ks[tid + i * 256]; vx[i] = vs[tid + i * 256]; }
        }

        // ---- S = Q K^T (ldmatrix.x4 B-fragments) ----
        const __half* kbuf = Ksb + buf * TILEH + offK;
        float sacc[8][4];
#pragma unroll
        for (int j = 0; j < 8; j++) {
            sacc[j][0] = 0.f; sacc[j][1] = 0.f; sacc[j][2] = 0.f; sacc[j][3] = 0.f;
        }
#pragma unroll
        for (int ks = 0; ks < 8; ks++) {
#pragma unroll
            for (int jp = 0; jp < 4; jp++) {
                unsigned b0, b1, b2, b3;
                ldsm_x4(b0, b1, b2, b3, kbuf + jp * (16 * KSTR) + ks * 16);
                mma16816(sacc[2 * jp + 0], qf[ks], b0, b1);
                mma16816(sacc[2 * jp + 1], qf[ks], b2, b3);
            }
        }

        // ---- add mask (x log2e, via FFMA) ----
        {
            const float* mr0 = Mb + (size_t)r0 * S_LEN + kt * NTILE;
            const float* mr1 = mr0 + (size_t)8 * S_LEN;
#pragma unroll
            for (int j = 0; j < 8; j++) {
                float2 u0 = *(const float2*)(mr0 + j * 8 + qc * 2);
                float2 u1 = *(const float2*)(mr1 + j * 8 + qc * 2);
                sacc[j][0] = fmaf(u0.x, LOG2E, sacc[j][0]);
                sacc[j][1] = fmaf(u0.y, LOG2E, sacc[j][1]);
                sacc[j][2] = fmaf(u1.x, LOG2E, sacc[j][2]);
                sacc[j][3] = fmaf(u1.y, LOG2E, sacc[j][3]);
            }
        }

        // ---- online softmax (exp2 domain) ----
        float tm0 = -INFINITY, tm1 = -INFINITY;
#pragma unroll
        for (int j = 0; j < 8; j++) {
            tm0 = fmaxf(tm0, fmaxf(sacc[j][0], sacc[j][1]));
            tm1 = fmaxf(tm1, fmaxf(sacc[j][2], sacc[j][3]));
        }
        tm0 = fmaxf(tm0, __shfl_xor_sync(0xffffffffu, tm0, 1));
        tm0 = fmaxf(tm0, __shfl_xor_sync(0xffffffffu, tm0, 2));
        tm1 = fmaxf(tm1, __shfl_xor_sync(0xffffffffu, tm1, 1));
        tm1 = fmaxf(tm1, __shfl_xor_sync(0xffffffffu, tm1, 2));

        const float nm0 = fmaxf(m0, tm0);
        const float nm1 = fmaxf(m1, tm1);
        const float al0 = ex2(m0 - nm0);   // ex2(-inf)=0 on first tile
        const float al1 = ex2(m1 - nm1);
        m0 = nm0; m1 = nm1;

        unsigned pA[4][4];
        float rs0 = 0.f, rs1 = 0.f;
#pragma unroll
        for (int j = 0; j < 8; j++) {
            float p0 = ex2(sacc[j][0] - nm0);
            float p1 = ex2(sacc[j][1] - nm0);
            float p2 = ex2(sacc[j][2] - nm1);
            float p3 = ex2(sacc[j][3] - nm1);
            rs0 += p0 + p1;
            rs1 += p2 + p3;
            pA[j >> 1][(j & 1) * 2 + 0] = pack_h2(p0, p1);
            pA[j >> 1][(j & 1) * 2 + 1] = pack_h2(p2, p3);
        }
        rs0 += __shfl_xor_sync(0xffffffffu, rs0, 1);
        rs0 += __shfl_xor_sync(0xffffffffu, rs0, 2);
        rs1 += __shfl_xor_sync(0xffffffffu, rs1, 1);
        rs1 += __shfl_xor_sync(0xffffffffu, rs1, 2);
        l0 = l0 * al0 + rs0;
        l1 = l1 * al1 + rs1;

#pragma unroll
        for (int nd = 0; nd < 16; nd++) {
            oacc[nd][0] *= al0; oacc[nd][1] *= al0;
            oacc[nd][2] *= al1; oacc[nd][3] *= al1;
        }

        // ---- O += P V (ldmatrix.x4.trans B-fragments) ----
        const __half* vbuf = Vsb + buf * TILEH + offV;
#pragma unroll
        for (int kt2 = 0; kt2 < 4; kt2++) {
#pragma unroll
            for (int ndp = 0; ndp < 8; ndp++) {
                unsigned b0, b1, b2, b3;
                ldsm_x4_t(b0, b1, b2, b3, vbuf + kt2 * (16 * KSTR) + ndp * 16);
                mma16816(oacc[2 * ndp + 0], pA[kt2], b0, b1);
                mma16816(oacc[2 * ndp + 1], pA[kt2], b2, b3);
            }
        }

        // ---- store prefetched tile into the other buffer ----
        if (pre) {
            __half* kd = Ksb + (buf ^ 1) * TILEH;
            __half* vd = Vsb + (buf ^ 1) * TILEH;
#pragma unroll
            for (int i = 0; i < 8; i++) {
                const int idx = tid + i * 256;
                const int kv = idx >> 5, d = (idx & 31) << 2;
                __half2* dk = (__half2*)(kd + kv * KSTR + d);
                dk[0] = __floats2half2_rn(kx[i].x, kx[i].y);
                dk[1] = __floats2half2_rn(kx[i].z, kx[i].w);
                __half2* dv = (__half2*)(vd + kv * KSTR + d);
                dv[0] = __floats2half2_rn(vx[i].x, vx[i].y);
                dv[1] = __floats2half2_rn(vx[i].z, vx[i].w);
            }
            __syncthreads();
        }
        buf ^= 1;
    }

    // ---- epilogue ----
    const float inv0 = 1.0f / l0;
    const float inv1 = 1.0f / l1;
#pragma unroll
    for (int nd = 0; nd < 16; nd++) {
        float2 w0 = make_float2(oacc[nd][0] * inv0, oacc[nd][1] * inv0);
        float2 w1 = make_float2(oacc[nd][2] * inv1, oacc[nd][3] * inv1);
        *(float2*)(Ob + (size_t)r0 * D_DIM + nd * 8 + qc * 2) = w0;
        *(float2*)(Ob + (size_t)(r0 + 8) * D_DIM + nd * 8 + qc * 2) = w1;
    }
}

extern "C" void kernel_launch(void* const* d_in, const int* in_sizes, int n_in,
                              void* d_out, int out_size) {
    const float* q = (const float*)d_in[0];
    const float* k = (const float*)d_in[1];
    const float* v = (const float*)d_in[2];
    const float* m = (const float*)d_in[3];
    float* out = (float*)d_out;

    cudaFuncSetAttribute(fa_fp16_kernel,
                         cudaFuncAttributeMaxDynamicSharedMemorySize, SMEM_BYTES);

    dim3 grid(S_LEN / MTILE, 64);
    dim3 block(256);
    fa_fp16_kernel<<<grid, block, SMEM_BYTES>>>(q, k, v, m, out);
}